// round 15
// baseline (speedup 1.0000x reference)
#include <cuda_runtime.h>
#include <cuda_fp16.h>

// Problem constants
#define BATCH 2
#define DIM   192
#define PLANE (DIM*DIM)           // 36864
#define VOL   (DIM*DIM*DIM)       // 7077888
#define NVOX  (BATCH*VOL)         // 14155776
#define RW    4                   // window radius (WIN=9)
#define WIN   9
#define INV729 (1.0f/729.0f)
#define EPSV  1e-5f
#define CHUNK 48                  // y/z chunk per block (192/48 = 4 chunks)
#define NCHUNK (DIM/CHUNK)
#define TPB12 96                  // pass12: 96 threads, each owns x = 2t, 2t+1
#define TPB3  192                 // pass3: 192 threads, one x each
#define NBLK  (BATCH*DIM*NCHUNK)  // 1536 pass3 blocks

// Intermediates (after fused x+y pass), interleaved per voxel:
//   gBab[v] = { half2(SumI,SumJ), half2(SumI2,SumJ2) }   (one LDG.64 in pass3)
//   gB4[v]  = half(SumIJ)
__device__ uint2  gBab[NVOX];
__device__ __half gB4 [NVOX];
__device__ float    g_part[NBLK]; // per-block partial ncc sums
__device__ unsigned g_done = 0;   // last-block counter (self-resetting)

__device__ __forceinline__ unsigned h2u(__half2 h) {
    return *reinterpret_cast<unsigned*>(&h);
}
__device__ __forceinline__ __half2 u2h(unsigned u) {
    return *reinterpret_cast<__half2*>(&u);
}

// ---------------------------------------------------------------------------
// Fused pass 1+2, x-coarsened x2. x-box in fp32 (smem row, shared 10-tap sum
// + endpoint corrections); y-box rolling sums in PACKED HALF2 registers
// (HADD2/HSUB2; ring stores the identical half2 values -> subtract removes
// exactly what was added). Ring + output use the interleaved {01,23} layout
// so ring traffic is uint4 (1 STS + 1 LDS saved per row) and the global
// store is STG.128 + STG.32. One __syncthreads per row (double-buffered).
// ---------------------------------------------------------------------------
__global__ __launch_bounds__(TPB12, 9) void k_pass12(
    const float* __restrict__ I, const float* __restrict__ J)
{
    __shared__ __align__(16) uint2  rab[WIN][DIM];  // 13.8 KB {E/O voxel pairs}
    __shared__ __half r4[WIN][DIM];                 // 3.5 KB (half2 at even x)
    __shared__ __align__(16) float sbuf[2][2][DIM + 2*RW]; // 6.4 KB

    const int bz = blockIdx.x;                    // b*DIM + z
    const int y0 = blockIdx.y * CHUNK;
    const int t  = threadIdx.x;
    const int x0 = 2 * t;
    const int pb = bz * PLANE;

    if (t < RW) {                                 // zero pads (both parities)
#pragma unroll
        for (int p = 0; p < 2; p++) {
            sbuf[p][0][t] = 0.f;            sbuf[p][1][t] = 0.f;
            sbuf[p][0][RW + DIM + t] = 0.f; sbuf[p][1][RW + DIM + t] = 0.f;
        }
    }

    // rolling sums, packed: E=(x0), O=(x0+1); s4EO = (E4, O4)
    const __half2 hz = __floats2half2_rn(0.f, 0.f);
    __half2 sE01 = hz, sE23 = hz, sO01 = hz, sO23 = hz, s4EO = hz;

    auto do_row = [&](int r) {
        float* sI = sbuf[r & 1][0];
        float* sJ = sbuf[r & 1][1];
        const float2 iv = *reinterpret_cast<const float2*>(&I[pb + r*DIM + x0]);
        const float2 jv = *reinterpret_cast<const float2*>(&J[pb + r*DIM + x0]);
        *reinterpret_cast<float2*>(&sI[RW + x0]) = iv;
        *reinterpret_cast<float2*>(&sJ[RW + x0]) = jv;
        __syncthreads();

        // 10 shared taps w[0..9] = sI[x0..x0+9] via 5 float2 loads (x0 even)
        float S0=0.f,S1=0.f,S2=0.f,S3=0.f,S4=0.f;
        float u0=0.f,v0=0.f,u9=0.f,v9=0.f;
#pragma unroll
        for (int k = 0; k < 10; k += 2) {
            const float2 uu = *reinterpret_cast<const float2*>(&sI[x0 + k]);
            const float2 vv = *reinterpret_cast<const float2*>(&sJ[x0 + k]);
            if (k == 0) { u0 = uu.x; v0 = vv.x; }
            if (k == 8) { u9 = uu.y; v9 = vv.y; }
            S0 += uu.x; S1 += vv.x; S2 += uu.x*uu.x; S3 += vv.x*vv.x; S4 += uu.x*vv.x;
            S0 += uu.y; S1 += vv.y; S2 += uu.y*uu.y; S3 += vv.y*vv.y; S4 += uu.y*vv.y;
        }
        // even = 10-tap sum minus tap9; odd = minus tap0. Pack once.
        const __half2 e01 = __floats2half2_rn(S0 - u9,    S1 - v9);
        const __half2 e23 = __floats2half2_rn(S2 - u9*u9, S3 - v9*v9);
        const __half2 o01 = __floats2half2_rn(S0 - u0,    S1 - v0);
        const __half2 o23 = __floats2half2_rn(S2 - u0*u0, S3 - v0*v0);
        const __half2 eo4 = __floats2half2_rn(S4 - u9*v9, S4 - u0*v0);

        const int sl = r % WIN;
        *reinterpret_cast<uint4*>(&rab[sl][x0]) =
            make_uint4(h2u(e01), h2u(e23), h2u(o01), h2u(o23));
        *reinterpret_cast<__half2*>(&r4[sl][x0]) = eo4;

        sE01 = __hadd2(sE01, e01); sE23 = __hadd2(sE23, e23);
        sO01 = __hadd2(sO01, o01); sO23 = __hadd2(sO23, o23);
        s4EO = __hadd2(s4EO, eo4);
    };

    const int rlo = (y0 - RW < 0) ? 0 : (y0 - RW);
    for (int r = rlo; r <= y0 + RW; r++) do_row(r);

    for (int y = y0; ; y++) {
        const int id = pb + y * DIM + x0;
        *reinterpret_cast<uint4*>(&gBab[id]) =
            make_uint4(h2u(sE01), h2u(sE23), h2u(sO01), h2u(sO23));
        *reinterpret_cast<__half2*>(&gB4[id]) = s4EO;
        if (y == y0 + CHUNK - 1) break;

        const int rs = y - RW;                    // leaving row
        if (rs >= 0) {
            const int sl = rs % WIN;
            const uint4 q = *reinterpret_cast<const uint4*>(&rab[sl][x0]);
            const __half2 q4 = *reinterpret_cast<const __half2*>(&r4[sl][x0]);
            sE01 = __hsub2(sE01, u2h(q.x)); sE23 = __hsub2(sE23, u2h(q.y));
            sO01 = __hsub2(sO01, u2h(q.z)); sO23 = __hsub2(sO23, u2h(q.w));
            s4EO = __hsub2(s4EO, q4);
        }
        const int ra = y + RW + 1;                // entering row
        if (ra < DIM) do_row(ra);
    }
}

// ---------------------------------------------------------------------------
// Pass 3: z-rolling sums with a REGISTER ring. The z-loop is fully unrolled;
// with a virtual zero-padded prologue (always 9 slots, rows < 0 contribute
// zero) the ring slot at step i is i%9 for both subtract and overwrite —
// compile-time after unroll, so the ring lives in registers and the old
// 3 STS + 3 LDS per step become register renames. Rows >= DIM are stored as
// zeros (never added, so subtracting them later is a no-op) — identical
// window semantics to the smem-ring version; arithmetic order unchanged.
// Grid-wide final reduction folded in (fence + atomic counter, deterministic,
// self-resetting).
// ---------------------------------------------------------------------------
__global__ __launch_bounds__(TPB3, 6) void k_pass3(float* __restrict__ out) {
    __shared__ float red[TPB3];
    __shared__ int   s_last;

    const int by = blockIdx.x;                    // b*DIM + y
    const int b  = by / DIM;
    const int y  = by % DIM;
    const int z0 = blockIdx.y * CHUNK;
    const int x  = threadIdx.x;
    const int base = b * VOL + y * DIM + x;

    const __half2 hz = __floats2half2_rn(0.f, 0.f);
    const __half  h0 = __float2half_rn(0.f);

    uint2  qab[WIN];                              // register ring
    __half q4 [WIN];
    __half2 s01 = hz, s23 = hz;
    __half  s4  = h0;

    // Prologue: 9 slots, rows z0-4 .. z0+4 (rows < 0 are virtual zeros).
#pragma unroll
    for (int l = 0; l < WIN; l++) {
        const int r = z0 - RW + l;                // always < DIM
        uint2 uab = make_uint2(0u, 0u);
        __half h4 = h0;
        if (r >= 0) {
            const int id = base + r * PLANE;
            uab = gBab[id];
            h4  = gB4[id];
        }
        qab[l] = uab; q4[l] = h4;
        s01 = __hadd2(s01, u2h(uab.x));
        s23 = __hadd2(s23, u2h(uab.y));
        s4  = __hadd(s4, h4);
    }

    float acc = 0.f;
#pragma unroll
    for (int i = 0; i < CHUNK; i++) {
        // Issue entering-row load first (overlaps LDG latency with math).
        const int  sl  = i % WIN;                 // static after unroll
        const bool upd = (i < CHUNK - 1);
        uint2 uab = make_uint2(0u, 0u);
        __half h4 = h0;
        const int ra = z0 + RW + 1 + i;
        if (upd && ra < DIM) {
            const int id = base + ra * PLANE;
            uab = gBab[id];
            h4  = gB4[id];
        }

        const float2 f01 = __half22float2(s01);
        const float2 f23 = __half22float2(s23);
        const float  f4  = __half2float(s4);
        const float uI = f01.x * INV729, uJ = f01.y * INV729;
        const float I2 = f23.x * INV729 - uI * uI;
        const float J2 = f23.y * INV729 - uJ * uJ;
        const float IJ = f4   * INV729 - uI * uJ;
        acc += (IJ * IJ) / (I2 * J2 + EPSV);

        if (upd) {
            s01 = __hsub2(s01, u2h(qab[sl].x));   // leaving row (exact)
            s23 = __hsub2(s23, u2h(qab[sl].y));
            s4  = __hsub(s4, q4[sl]);
            qab[sl] = uab; q4[sl] = h4;           // entering row -> same slot
            s01 = __hadd2(s01, u2h(uab.x));
            s23 = __hadd2(s23, u2h(uab.y));
            s4  = __hadd(s4, h4);
        }
    }

    // Block tree-reduce 192 partials (192 = 3 * 2^6), deterministic order.
    red[x] = acc;
    __syncthreads();
#pragma unroll
    for (int s = 96; s >= 3; s >>= 1) {
        if (x < s) red[x] += red[x + s];
        __syncthreads();
    }
    if (x == 0) {
        g_part[blockIdx.y * (BATCH * DIM) + blockIdx.x] = red[0] + red[1] + red[2];
        __threadfence();
        const unsigned v = atomicAdd(&g_done, 1u);
        s_last = (v == NBLK - 1);
    }
    __syncthreads();

    if (s_last) {                                 // exactly one block runs this
        float a = 0.f;
        for (int i = x; i < NBLK; i += TPB3) a += g_part[i];
        red[x] = a;
        __syncthreads();
#pragma unroll
        for (int s = 96; s >= 3; s >>= 1) {
            if (x < s) red[x] += red[x + s];
            __syncthreads();
        }
        if (x == 0) {
            out[0] = -(red[0] + red[1] + red[2]) * (1.0f / (float)NVOX);
            g_done = 0;                           // reset for next graph replay
        }
    }
}

extern "C" void kernel_launch(void* const* d_in, const int* in_sizes, int n_in,
                              void* d_out, int out_size) {
    const float* y_pred = (const float*)d_in[0];
    const float* y_true = (const float*)d_in[1];
    float* out = (float*)d_out;

    k_pass12<<<dim3(BATCH * DIM, NCHUNK), TPB12>>>(y_pred, y_true);
    k_pass3 <<<dim3(BATCH * DIM, NCHUNK), TPB3>>>(out);
}

// round 16
// speedup vs baseline: 1.3435x; 1.3435x over previous
#include <cuda_runtime.h>
#include <cuda_fp16.h>

// Problem constants
#define BATCH 2
#define DIM   192
#define PLANE (DIM*DIM)           // 36864
#define VOL   (DIM*DIM*DIM)       // 7077888
#define NVOX  (BATCH*VOL)         // 14155776
#define RW    4                   // window radius (WIN=9)
#define WIN   9
#define INV729 (1.0f/729.0f)
#define EPSV  1e-5f
#define CHUNK 48                  // y/z chunk per block (192/48 = 4 chunks)
#define NCHUNK (DIM/CHUNK)
#define TPB12 96                  // pass12: 96 threads, each owns x = 2t, 2t+1
#define TPB3  192                 // pass3: 192 threads, one x each
#define NBLK  (BATCH*DIM*NCHUNK)  // 1536 pass3 blocks
#define PF    4                   // pass3 prefetch group size (double-buffered)

// Intermediates (after fused x+y pass), interleaved per voxel:
//   gBab[v] = { half2(SumI,SumJ), half2(SumI2,SumJ2) }   (one LDG.64 in pass3)
//   gB4[v]  = half(SumIJ)
__device__ uint2  gBab[NVOX];
__device__ __half gB4 [NVOX];
__device__ float    g_part[NBLK]; // per-block partial ncc sums
__device__ unsigned g_done = 0;   // last-block counter (self-resetting)

__device__ __forceinline__ unsigned h2u(__half2 h) {
    return *reinterpret_cast<unsigned*>(&h);
}
__device__ __forceinline__ __half2 u2h(unsigned u) {
    return *reinterpret_cast<__half2*>(&u);
}

// ---------------------------------------------------------------------------
// Fused pass 1+2, x-coarsened x2, with ONE-ROW REGISTER PREFETCH: row r+1's
// global loads are issued before row r's barrier + tap computation, so the
// LDG latency is covered by a full row of work instead of being exposed at
// the STS each row. Arithmetic identical to the previous version.
// ---------------------------------------------------------------------------
__global__ __launch_bounds__(TPB12, 9) void k_pass12(
    const float* __restrict__ I, const float* __restrict__ J)
{
    __shared__ __align__(16) uint2  rab[WIN][DIM];  // 13.8 KB {E/O voxel pairs}
    __shared__ __half r4[WIN][DIM];                 // 3.5 KB (half2 at even x)
    __shared__ __align__(16) float sbuf[2][2][DIM + 2*RW]; // 6.4 KB

    const int bz = blockIdx.x;                    // b*DIM + z
    const int y0 = blockIdx.y * CHUNK;
    const int t  = threadIdx.x;
    const int x0 = 2 * t;
    const int pb = bz * PLANE;

    if (t < RW) {                                 // zero pads (both parities)
#pragma unroll
        for (int p = 0; p < 2; p++) {
            sbuf[p][0][t] = 0.f;            sbuf[p][1][t] = 0.f;
            sbuf[p][0][RW + DIM + t] = 0.f; sbuf[p][1][RW + DIM + t] = 0.f;
        }
    }

    // rolling sums, packed: E=(x0), O=(x0+1); s4EO = (E4, O4)
    const __half2 hz = __floats2half2_rn(0.f, 0.f);
    __half2 sE01 = hz, sE23 = hz, sO01 = hz, sO23 = hz, s4EO = hz;

    const int rlo  = (y0 - RW < 0) ? 0 : (y0 - RW);
    const int rmax = (y0 + CHUNK - 1 + RW < DIM - 1) ? (y0 + CHUNK - 1 + RW)
                                                     : (DIM - 1);

    // prefetched input row (registers)
    float2 p_iv = *reinterpret_cast<const float2*>(&I[pb + rlo*DIM + x0]);
    float2 p_jv = *reinterpret_cast<const float2*>(&J[pb + rlo*DIM + x0]);

    // Process row r using the prefetched registers; issue prefetch for r+1
    // BEFORE the barrier so its latency overlaps bar + taps.
    auto proc = [&](int r) {
        float* sI = sbuf[r & 1][0];
        float* sJ = sbuf[r & 1][1];
        *reinterpret_cast<float2*>(&sI[RW + x0]) = p_iv;
        *reinterpret_cast<float2*>(&sJ[RW + x0]) = p_jv;
        if (r < rmax) {                           // prefetch next row
            p_iv = *reinterpret_cast<const float2*>(&I[pb + (r+1)*DIM + x0]);
            p_jv = *reinterpret_cast<const float2*>(&J[pb + (r+1)*DIM + x0]);
        }
        __syncthreads();

        // 10 shared taps w[0..9] = sI[x0..x0+9] via 5 float2 loads (x0 even)
        float S0=0.f,S1=0.f,S2=0.f,S3=0.f,S4=0.f;
        float u0=0.f,v0=0.f,u9=0.f,v9=0.f;
#pragma unroll
        for (int k = 0; k < 10; k += 2) {
            const float2 uu = *reinterpret_cast<const float2*>(&sI[x0 + k]);
            const float2 vv = *reinterpret_cast<const float2*>(&sJ[x0 + k]);
            if (k == 0) { u0 = uu.x; v0 = vv.x; }
            if (k == 8) { u9 = uu.y; v9 = vv.y; }
            S0 += uu.x; S1 += vv.x; S2 += uu.x*uu.x; S3 += vv.x*vv.x; S4 += uu.x*vv.x;
            S0 += uu.y; S1 += vv.y; S2 += uu.y*uu.y; S3 += vv.y*vv.y; S4 += uu.y*vv.y;
        }
        // even = 10-tap sum minus tap9; odd = minus tap0. Pack once.
        const __half2 e01 = __floats2half2_rn(S0 - u9,    S1 - v9);
        const __half2 e23 = __floats2half2_rn(S2 - u9*u9, S3 - v9*v9);
        const __half2 o01 = __floats2half2_rn(S0 - u0,    S1 - v0);
        const __half2 o23 = __floats2half2_rn(S2 - u0*u0, S3 - v0*v0);
        const __half2 eo4 = __floats2half2_rn(S4 - u9*v9, S4 - u0*v0);

        const int sl = r % WIN;
        *reinterpret_cast<uint4*>(&rab[sl][x0]) =
            make_uint4(h2u(e01), h2u(e23), h2u(o01), h2u(o23));
        *reinterpret_cast<__half2*>(&r4[sl][x0]) = eo4;

        sE01 = __hadd2(sE01, e01); sE23 = __hadd2(sE23, e23);
        sO01 = __hadd2(sO01, o01); sO23 = __hadd2(sO23, o23);
        s4EO = __hadd2(s4EO, eo4);
    };

    for (int r = rlo; r <= y0 + RW; r++) proc(r);

    for (int y = y0; ; y++) {
        const int id = pb + y * DIM + x0;
        *reinterpret_cast<uint4*>(&gBab[id]) =
            make_uint4(h2u(sE01), h2u(sE23), h2u(sO01), h2u(sO23));
        *reinterpret_cast<__half2*>(&gB4[id]) = s4EO;
        if (y == y0 + CHUNK - 1) break;

        const int rs = y - RW;                    // leaving row
        if (rs >= 0) {
            const int sl = rs % WIN;
            const uint4 q = *reinterpret_cast<const uint4*>(&rab[sl][x0]);
            const __half2 q4 = *reinterpret_cast<const __half2*>(&r4[sl][x0]);
            sE01 = __hsub2(sE01, u2h(q.x)); sE23 = __hsub2(sE23, u2h(q.y));
            sO01 = __hsub2(sO01, u2h(q.z)); sO23 = __hsub2(sO23, u2h(q.w));
            s4EO = __hsub2(s4EO, q4);
        }
        const int ra = y + RW + 1;                // entering row
        if (ra < DIM) proc(ra);
    }
}

// ---------------------------------------------------------------------------
// Pass 3: z-rolling sums with a register ring (fully unrolled, slot = i%9
// static) + DOUBLE-BUFFERED GROUP PREFETCH: loads for iteration group g+1
// are issued at the start of group g into the alternate register buffer, so
// each load has >= PF iterations (~150-300 cyc) to complete and PF loads are
// in flight per thread. Arithmetic order identical to the previous version.
// Grid-wide final reduction folded in (fence + atomic counter, deterministic,
// self-resetting).
// ---------------------------------------------------------------------------
__global__ __launch_bounds__(TPB3, 4) void k_pass3(float* __restrict__ out) {
    __shared__ float red[TPB3];
    __shared__ int   s_last;

    const int by = blockIdx.x;                    // b*DIM + y
    const int b  = by / DIM;
    const int y  = by % DIM;
    const int z0 = blockIdx.y * CHUNK;
    const int x  = threadIdx.x;
    const int base = b * VOL + y * DIM + x;

    const __half2 hz = __floats2half2_rn(0.f, 0.f);
    const __half  h0 = __float2half_rn(0.f);

    uint2  qab[WIN];                              // register ring
    __half q4 [WIN];
    __half2 s01 = hz, s23 = hz;
    __half  s4  = h0;

    // Prologue: 9 slots, rows z0-4 .. z0+4 (rows < 0 are virtual zeros).
#pragma unroll
    for (int l = 0; l < WIN; l++) {
        const int r = z0 - RW + l;                // always < DIM
        uint2 uab = make_uint2(0u, 0u);
        __half h4 = h0;
        if (r >= 0) {
            const int id = base + r * PLANE;
            uab = gBab[id];
            h4  = gB4[id];
        }
        qab[l] = uab; q4[l] = h4;
        s01 = __hadd2(s01, u2h(uab.x));
        s23 = __hadd2(s23, u2h(uab.y));
        s4  = __hadd(s4, h4);
    }

    // Double-buffered prefetch registers: pf[parity][j] holds the entering
    // row for iteration g*PF + j, parity = g & 1.
    uint2  pf_ab[2][PF];
    __half pf_4 [2][PF];

    // Load the entering row for iteration k (zeros if none).
    auto pload = [&](int k, uint2& uab, __half& h4) {
        uab = make_uint2(0u, 0u);
        h4  = h0;
        if (k < CHUNK - 1) {
            const int ra = z0 + RW + 1 + k;
            if (ra < DIM) {
                const int id = base + ra * PLANE;
                uab = gBab[id];
                h4  = gB4[id];
            }
        }
    };

    // Preload group 0.
#pragma unroll
    for (int j = 0; j < PF; j++) pload(j, pf_ab[0][j], pf_4[0][j]);

    float acc = 0.f;
#pragma unroll
    for (int i = 0; i < CHUNK; i++) {
        const int g  = i / PF;                    // static after unroll
        const int pj = i % PF;
        if (pj == 0) {                            // prefetch group g+1
            const int np = (g + 1) & 1;
#pragma unroll
            for (int j = 0; j < PF; j++)
                pload((g + 1) * PF + j, pf_ab[np][j], pf_4[np][j]);
        }

        const float2 f01 = __half22float2(s01);
        const float2 f23 = __half22float2(s23);
        const float  f4  = __half2float(s4);
        const float uI = f01.x * INV729, uJ = f01.y * INV729;
        const float I2 = f23.x * INV729 - uI * uI;
        const float J2 = f23.y * INV729 - uJ * uJ;
        const float IJ = f4   * INV729 - uI * uJ;
        acc += (IJ * IJ) / (I2 * J2 + EPSV);

        if (i < CHUNK - 1) {
            const int sl = i % WIN;               // static after unroll
            const int cp = g & 1;
            s01 = __hsub2(s01, u2h(qab[sl].x));   // leaving row (exact)
            s23 = __hsub2(s23, u2h(qab[sl].y));
            s4  = __hsub(s4, q4[sl]);
            qab[sl] = pf_ab[cp][pj];              // entering row -> same slot
            q4 [sl] = pf_4 [cp][pj];
            s01 = __hadd2(s01, u2h(qab[sl].x));
            s23 = __hadd2(s23, u2h(qab[sl].y));
            s4  = __hadd(s4, q4[sl]);
        }
    }

    // Block tree-reduce 192 partials (192 = 3 * 2^6), deterministic order.
    red[x] = acc;
    __syncthreads();
#pragma unroll
    for (int s = 96; s >= 3; s >>= 1) {
        if (x < s) red[x] += red[x + s];
        __syncthreads();
    }
    if (x == 0) {
        g_part[blockIdx.y * (BATCH * DIM) + blockIdx.x] = red[0] + red[1] + red[2];
        __threadfence();
        const unsigned v = atomicAdd(&g_done, 1u);
        s_last = (v == NBLK - 1);
    }
    __syncthreads();

    if (s_last) {                                 // exactly one block runs this
        float a = 0.f;
        for (int i = x; i < NBLK; i += TPB3) a += g_part[i];
        red[x] = a;
        __syncthreads();
#pragma unroll
        for (int s = 96; s >= 3; s >>= 1) {
            if (x < s) red[x] += red[x + s];
            __syncthreads();
        }
        if (x == 0) {
            out[0] = -(red[0] + red[1] + red[2]) * (1.0f / (float)NVOX);
            g_done = 0;                           // reset for next graph replay
        }
    }
}

extern "C" void kernel_launch(void* const* d_in, const int* in_sizes, int n_in,
                              void* d_out, int out_size) {
    const float* y_pred = (const float*)d_in[0];
    const float* y_true = (const float*)d_in[1];
    float* out = (float*)d_out;

    k_pass12<<<dim3(BATCH * DIM, NCHUNK), TPB12>>>(y_pred, y_true);
    k_pass3 <<<dim3(BATCH * DIM, NCHUNK), TPB3>>>(out);
}